// round 13
// baseline (speedup 1.0000x reference)
#include <cuda_runtime.h>
#include <math.h>

#define C_DT    0.01f
#define C_STEPS 100
#define C_HALF  50
#define C_NOSC  50
#define C_NPER  50
#define C_LIM   1.0471975511965976f   /* pi/3 */
#define C_MGL2  4.905f                /* m*g*(l/2), I = 1 */
#define NBP     13                    /* producer blocks: 4 oscillators each (52, 2 padded) */

/* [step][128]: slots bid*8 + q*2 + quad (104 used); never-written slots stay 0 */
__device__ __align__(128) float g_tq[C_STEPS * 128];
__device__ unsigned g_ph[2];          /* phase counters; consumer resets each run */

typedef unsigned long long u64t;

__device__ __forceinline__ u64t pk2(float lo, float hi) {
    u64t r; asm("mov.b64 %0, {%1, %2};" : "=l"(r) : "f"(lo), "f"(hi)); return r;
}
__device__ __forceinline__ void upk2(u64t v, float& lo, float& hi) {
    asm("mov.b64 {%0, %1}, %2;" : "=f"(lo), "=f"(hi) : "l"(v));
}
__device__ __forceinline__ u64t fma2(u64t a, u64t b, u64t c) {
    u64t d; asm("fma.rn.f32x2 %0, %1, %2, %3;" : "=l"(d) : "l"(a), "l"(b), "l"(c)); return d;
}
__device__ __forceinline__ u64t add2(u64t a, u64t b) {
    u64t d; asm("add.rn.f32x2 %0, %1, %2;" : "=l"(d) : "l"(a), "l"(b)); return d;
}

__global__ __launch_bounds__(128, 1)
void cpg_fused(const float* __restrict__ x,
               const float* __restrict__ fc1_w, const float* __restrict__ fc1_b,
               const float* __restrict__ fc2_w, const float* __restrict__ fc2_b,
               const float* __restrict__ fc3_w, const float* __restrict__ fc3_b,
               const float* __restrict__ fcd_w, const float* __restrict__ fcd_b,
               const float* __restrict__ fc4_w, const float* __restrict__ fc4_b,
               const float* __restrict__ enc,  const float* __restrict__ osc_bias,
               const float* __restrict__ dec,
               float* __restrict__ out)
{
    const int tid = threadIdx.x;
    const int bid = blockIdx.x;
    const float x0 = x[0], x1 = x[1];

    if (bid < NBP) {
        // ============================ PRODUCER ============================
        __shared__ float sh_h[128];
        __shared__ float sh_h2[128];
        __shared__ float sh_o[8];

        // warp0: packed per-neuron constants. 8 lanes/osc, 4 osc/warp, 7 neurons/lane.
        u64t E2[7], BB2[7], DE2[7], D2[7];
        float w4[7];
        if (tid < 32) {
            const int q   = tid >> 3;
            const int l8  = tid & 7;
            const int osc = bid * 4 + q;
            #pragma unroll
            for (int k = 0; k < 7; ++k) {
                int n = l8 + 8 * k;
                float e0v = 0.f, e1v = 0.f, bbv = 0.f, d0v = 0.f, d1v = 0.f, w4v = 0.f;
                if (osc < C_NOSC && n < C_NPER) {
                    int idx = osc * C_NPER + n;
                    e0v = enc[idx * 2 + 0];
                    e1v = enc[idx * 2 + 1];
                    bbv = osc_bias[idx];
                    d0v = dec[osc * 2 * C_NPER + n];
                    d1v = dec[osc * 2 * C_NPER + C_NPER + n];
                    w4v = fc4_w[idx];
                }
                E2[k]  = pk2(e0v, e1v);
                BB2[k] = pk2(bbv, 0.f);
                DE2[k] = pk2(C_DT * e0v, C_DT * e1v);
                D2[k]  = pk2(d0v, d1v);
                w4[k]  = w4v;
            }
        }

        // prefetch 8 fc2 float4s above the first barrier
        const float4* wr2 = (const float4*)(fc2_w + tid * 128);
        float4 pre0 = wr2[0], pre1 = wr2[1], pre2 = wr2[2], pre3 = wr2[3];
        float4 pre4 = wr2[4], pre5 = wr2[5], pre6 = wr2[6], pre7 = wr2[7];

        // h = relu(fc1 x + b1)
        {
            float v = fmaf(fc1_w[tid * 2], x0, fmaf(fc1_w[tid * 2 + 1], x1, fc1_b[tid]));
            sh_h[tid] = fmaxf(v, 0.f);
        }
        __syncthreads();

        // h2 = relu(fc2 h + b2)
        {
            float a0 = 0.f, a1 = 0.f, a2 = 0.f, a3 = 0.f;
            const float4 pre[8] = {pre0, pre1, pre2, pre3, pre4, pre5, pre6, pre7};
            #pragma unroll
            for (int j = 0; j < 8; ++j) {
                float4 w = pre[j];
                a0 = fmaf(w.x, sh_h[4 * j + 0], a0);
                a1 = fmaf(w.y, sh_h[4 * j + 1], a1);
                a2 = fmaf(w.z, sh_h[4 * j + 2], a2);
                a3 = fmaf(w.w, sh_h[4 * j + 3], a3);
            }
            #pragma unroll 8
            for (int j = 8; j < 32; ++j) {
                float4 w = wr2[j];
                a0 = fmaf(w.x, sh_h[4 * j + 0], a0);
                a1 = fmaf(w.y, sh_h[4 * j + 1], a1);
                a2 = fmaf(w.z, sh_h[4 * j + 2], a2);
                a3 = fmaf(w.w, sh_h[4 * j + 3], a3);
            }
            sh_h2[tid] = fmaxf((a0 + a1) + (a2 + a3) + fc2_b[tid], 0.f);
        }
        __syncthreads();

        // warp1: this block's 8 fc3 rows -> o0 (guard row < 100)
        if (tid >= 32 && tid < 64) {
            const int r     = (tid - 32) >> 2;
            const int lane4 = tid & 3;
            const int row   = bid * 8 + r;
            float s = 0.f;
            if (row < 2 * C_NOSC) {
                const float* wr = fc3_w + row * 128 + lane4 * 32;
                const float* hv = sh_h2 + lane4 * 32;
                #pragma unroll 8
                for (int k = 0; k < 32; ++k) s = fmaf(wr[k], hv[k], s);
            }
            s += __shfl_down_sync(0xffffffffu, s, 2, 4);
            s += __shfl_down_sync(0xffffffffu, s, 1, 4);
            if (lane4 == 0) sh_o[r] = (row < 2 * C_NOSC) ? s + fc3_b[row] : 0.f;
        }
        __syncthreads();

        // warp0: 100-step recurrence, deferred 3rd level + f32x2 packed math.
        if (tid < 32) {
            const int q  = tid >> 3;
            const int l8 = tid & 7;
            const u64t DT2 = pk2(C_DT, C_DT);

            u64t U  = pk2(sh_o[2 * q], sh_o[2 * q + 1]);  // u(t-1); init o0 (B=0)
            u64t Bv = pk2(0.f, 0.f);                       // carried cross-quad sums
            float* slot = g_tq + bid * 8 + q * 2 + (l8 >> 2);

            for (int s = 0; s < C_STEPS; ++s) {
                // full state s(t) = u + DT*B — off the encode path
                u64t Sfull = fma2(DT2, Bv, U);

                // encode: P from U (ready early); fold Bv (arrives late) second
                u64t ACCa = pk2(0.f, 0.f), ACCb = pk2(0.f, 0.f);
                float ata = 0.f, atb = 0.f;
                #pragma unroll
                for (int k = 0; k < 4; ++k) {
                    u64t P = fma2(E2[k], U, BB2[k]);
                    u64t Z = fma2(DE2[k], Bv, P);
                    float zl, zh; upk2(Z, zl, zh);
                    float a = fmaxf(zl + zh, 0.f);
                    u64t A2 = pk2(a, a);
                    ACCa = fma2(D2[k], A2, ACCa);
                    ata  = fmaf(w4[k], a, ata);
                }
                #pragma unroll
                for (int k = 4; k < 7; ++k) {
                    u64t P = fma2(E2[k], U, BB2[k]);
                    u64t Z = fma2(DE2[k], Bv, P);
                    float zl, zh; upk2(Z, zl, zh);
                    float a = fmaxf(zl + zh, 0.f);
                    u64t A2 = pk2(a, a);
                    ACCb = fma2(D2[k], A2, ACCb);
                    atb  = fmaf(w4[k], a, atb);
                }
                u64t ACC = add2(ACCa, ACCb);
                float a0, a1; upk2(ACC, a0, a1);
                float at = ata + atb;

                // 2-level butterfly -> quad sums (recurrence closes here)
                a0 += __shfl_xor_sync(0xffffffffu, a0, 1, 8);
                a1 += __shfl_xor_sync(0xffffffffu, a1, 1, 8);
                at += __shfl_xor_sync(0xffffffffu, at, 1, 8);
                a0 += __shfl_xor_sync(0xffffffffu, a0, 2, 8);
                a1 += __shfl_xor_sync(0xffffffffu, a1, 2, 8);
                at += __shfl_xor_sync(0xffffffffu, at, 2, 8);

                // cross-quad exchange: latency hidden under next step's FMA phase
                float nB0 = __shfl_xor_sync(0xffffffffu, a0, 4, 8);
                float nB1 = __shfl_xor_sync(0xffffffffu, a1, 4, 8);

                U  = fma2(DT2, pk2(a0, a1), Sfull);
                Bv = pk2(nB0, nB1);

                if ((l8 & 3) == 0) slot[s * 128] = at;  // two quad-partials per osc

                if (s == C_HALF - 1) {                  // publish phase 0
                    __threadfence();
                    __syncwarp();
                    if (tid == 0) atomicAdd(&g_ph[0], 1u);
                }
            }
            __threadfence();
            __syncwarp();
            if (tid == 0) atomicAdd(&g_ph[1], 1u);      // publish phase 1
        }
    } else {
        // ============================ CONSUMER ============================
        __shared__ float sh_h[128];
        __shared__ float sh_direct;
        __shared__ float sh_torque[C_STEPS];
        __shared__ float sh_l[2 * C_STEPS];

        // h = relu(fc1 x + b1); warp0 computes direct (overlaps producers)
        {
            float v = fmaf(fc1_w[tid * 2], x0, fmaf(fc1_w[tid * 2 + 1], x1, fc1_b[tid]));
            sh_h[tid] = fmaxf(v, 0.f);
        }
        __syncthreads();
        if (tid < 32) {
            float s = 0.f;
            #pragma unroll
            for (int k = 0; k < 4; ++k)
                s = fmaf(fcd_w[tid + 32 * k], sh_h[tid + 32 * k], s);
            #pragma unroll
            for (int off = 16; off; off >>= 1)
                s += __shfl_down_sync(0xffffffffu, s, off);
            if (tid == 0) sh_direct = s + fcd_b[0] + fc4_b[0];
        }
        __syncthreads();
        const float direct = sh_direct;

        float th = x0, om = 0.f;        // tid 0's limb state across phases
        float sv = __sinf(x0);          // software-pipelined sine

        #pragma unroll
        for (int p = 0; p < 2; ++p) {
            // single-thread, single-line, sleepy poll — bounded so a lost producer
            // can never hang the container (bound >> any legitimate wait)
            if (tid == 0) {
                unsigned v = 0;
                const unsigned* cp = &g_ph[p];
                for (long it = 0; it < 50000000L; ++it) {
                    asm volatile("ld.acquire.gpu.global.u32 %0, [%1];" : "=r"(v) : "l"(cp));
                    if (v >= NBP) break;
                    __nanosleep(64);
                }
            }
            __syncthreads();

            // 50 threads: reduce this phase's 104 quad-partials per step
            if (tid < C_HALF) {
                const int t = p * C_HALF + tid;
                const float4* row = (const float4*)(g_tq + t * 128);
                float acc = 0.f;
                #pragma unroll
                for (int j = 0; j < 26; ++j) {
                    float4 v = row[j];
                    acc += (v.x + v.y) + (v.z + v.w);
                }
                sh_torque[t] = acc + direct;
            }
            __syncthreads();

            // tid 0: limb integration for this phase (sin pipelined one step ahead)
            if (tid == 0) {
                #pragma unroll 5
                for (int i = 0; i < C_HALF; ++i) {
                    const int t = p * C_HALF + i;
                    float torque = sh_torque[t];
                    float th2 = fmaf(C_DT, om, th);
                    float om2 = fmaf(C_DT, torque - C_MGL2 * sv, om);
                    bool hit = (th2 > C_LIM) || (th2 < -C_LIM);
                    th2 = fminf(fmaxf(th2, -C_LIM), C_LIM);
                    om2 = hit ? 0.f : om2;
                    sh_l[2 * t]     = th2;
                    sh_l[2 * t + 1] = om2;
                    th = th2; om = om2;
                    sv = __sinf(th);
                }
            }
        }
        __syncthreads();

        // reset phase counters for the next graph replay (all producers done)
        if (tid < 2) g_ph[tid] = 0;

        // race-free coalesced output: out[0..199]=l_states, out[200..299]=torques
        out[tid] = sh_l[tid];
        if (tid < 72)  out[128 + tid] = sh_l[128 + tid];
        if (tid < 100) out[200 + tid] = sh_torque[tid];
    }
}

extern "C" void kernel_launch(void* const* d_in, const int* in_sizes, int n_in,
                              void* d_out, int out_size) {
    const float* x        = (const float*)d_in[0];
    const float* fc1_w    = (const float*)d_in[1];
    const float* fc1_b    = (const float*)d_in[2];
    const float* fc2_w    = (const float*)d_in[3];
    const float* fc2_b    = (const float*)d_in[4];
    const float* fc3_w    = (const float*)d_in[5];
    const float* fc3_b    = (const float*)d_in[6];
    const float* fcd_w    = (const float*)d_in[7];
    const float* fcd_b    = (const float*)d_in[8];
    const float* fc4_w    = (const float*)d_in[9];
    const float* fc4_b    = (const float*)d_in[10];
    const float* enc      = (const float*)d_in[11];
    const float* osc_bias = (const float*)d_in[12];
    const float* dec      = (const float*)d_in[13];
    float* out = (float*)d_out;

    cpg_fused<<<NBP + 1, 128>>>(x, fc1_w, fc1_b, fc2_w, fc2_b, fc3_w, fc3_b,
                                fcd_w, fcd_b, fc4_w, fc4_b, enc, osc_bias, dec, out);
}

// round 15
// speedup vs baseline: 1.1030x; 1.1030x over previous
#include <cuda_runtime.h>
#include <math.h>

#define C_DT    0.01f
#define C_STEPS 100
#define C_HALF  50
#define C_NOSC  50
#define C_NPER  50
#define C_LIM   1.0471975511965976f   /* pi/3 */
#define C_MGL2  4.905f                /* m*g*(l/2), I = 1 */
#define NBP     13                    /* producer blocks: 4 oscillators each (52, 2 padded) */

/* [step][128]: slots bid*8 + q*2 + quad (104 used); never-written slots stay 0 */
__device__ __align__(128) float g_tq[C_STEPS * 128];
__device__ unsigned g_ph[2];          /* phase counters; consumer resets each run */

__global__ __launch_bounds__(128, 1)
void cpg_fused(const float* __restrict__ x,
               const float* __restrict__ fc1_w, const float* __restrict__ fc1_b,
               const float* __restrict__ fc2_w, const float* __restrict__ fc2_b,
               const float* __restrict__ fc3_w, const float* __restrict__ fc3_b,
               const float* __restrict__ fcd_w, const float* __restrict__ fcd_b,
               const float* __restrict__ fc4_w, const float* __restrict__ fc4_b,
               const float* __restrict__ enc,  const float* __restrict__ osc_bias,
               const float* __restrict__ dec,
               float* __restrict__ out)
{
    const int tid = threadIdx.x;
    const int bid = blockIdx.x;
    const float x0 = x[0], x1 = x[1];

    if (bid < NBP) {
        // ============================ PRODUCER ============================
        __shared__ float sh_h[128];
        __shared__ float sh_h2[128];
        __shared__ float sh_o[8];

        // warp0: per-neuron constants. 8 lanes/osc, 4 osc/warp, 7 neurons/lane.
        float e0[7], e1[7], bb[7], d0[7], d1[7], w4[7];
        if (tid < 32) {
            const int q   = tid >> 3;
            const int l8  = tid & 7;
            const int osc = bid * 4 + q;
            #pragma unroll
            for (int k = 0; k < 7; ++k) {
                int n = l8 + 8 * k;
                if (osc < C_NOSC && n < C_NPER) {
                    int idx = osc * C_NPER + n;
                    e0[k] = enc[idx * 2 + 0];
                    e1[k] = enc[idx * 2 + 1];
                    bb[k] = osc_bias[idx];
                    d0[k] = dec[osc * 2 * C_NPER + n];
                    d1[k] = dec[osc * 2 * C_NPER + C_NPER + n];
                    w4[k] = fc4_w[idx];
                } else {
                    e0[k] = e1[k] = bb[k] = d0[k] = d1[k] = w4[k] = 0.f;
                }
            }
        }

        // prefetch 16 fc2 float4s above the first barrier (independent of h)
        const float4* wr2 = (const float4*)(fc2_w + tid * 128);
        float4 pre[16];
        #pragma unroll
        for (int j = 0; j < 16; ++j) pre[j] = wr2[j];

        // h = relu(fc1 x + b1)
        {
            float v = fmaf(fc1_w[tid * 2], x0, fmaf(fc1_w[tid * 2 + 1], x1, fc1_b[tid]));
            sh_h[tid] = fmaxf(v, 0.f);
        }
        __syncthreads();

        // h2 = relu(fc2 h + b2)
        {
            float a0 = 0.f, a1 = 0.f, a2 = 0.f, a3 = 0.f;
            #pragma unroll
            for (int j = 0; j < 16; ++j) {
                float4 w = pre[j];
                a0 = fmaf(w.x, sh_h[4 * j + 0], a0);
                a1 = fmaf(w.y, sh_h[4 * j + 1], a1);
                a2 = fmaf(w.z, sh_h[4 * j + 2], a2);
                a3 = fmaf(w.w, sh_h[4 * j + 3], a3);
            }
            #pragma unroll 8
            for (int j = 16; j < 32; ++j) {
                float4 w = wr2[j];
                a0 = fmaf(w.x, sh_h[4 * j + 0], a0);
                a1 = fmaf(w.y, sh_h[4 * j + 1], a1);
                a2 = fmaf(w.z, sh_h[4 * j + 2], a2);
                a3 = fmaf(w.w, sh_h[4 * j + 3], a3);
            }
            sh_h2[tid] = fmaxf((a0 + a1) + (a2 + a3) + fc2_b[tid], 0.f);
        }
        __syncthreads();

        // warp1: this block's 8 fc3 rows -> o0 (guard row < 100)
        if (tid >= 32 && tid < 64) {
            const int r     = (tid - 32) >> 2;
            const int lane4 = tid & 3;
            const int row   = bid * 8 + r;
            float s = 0.f;
            if (row < 2 * C_NOSC) {
                const float* wr = fc3_w + row * 128 + lane4 * 32;
                const float* hv = sh_h2 + lane4 * 32;
                #pragma unroll 8
                for (int k = 0; k < 32; ++k) s = fmaf(wr[k], hv[k], s);
            }
            s += __shfl_down_sync(0xffffffffu, s, 2, 4);
            s += __shfl_down_sync(0xffffffffu, s, 1, 4);
            if (lane4 == 0) sh_o[r] = (row < 2 * C_NOSC) ? s + fc3_b[row] : 0.f;
        }
        __syncthreads();

        // warp0: 100-step recurrence, two branch-free 50-step halves.
        if (tid < 32) {
            const int q  = tid >> 3;
            const int l8 = tid & 7;
            float s0 = sh_o[2 * q];
            float s1 = sh_o[2 * q + 1];
            float* slot = g_tq + bid * 8 + q * 2 + (l8 >> 2);

#define OSC_STEP(sidx)                                                        \
            {                                                                 \
                float a0a = 0.f, a1a = 0.f, ata = 0.f;                        \
                float a0b = 0.f, a1b = 0.f, atb = 0.f;                        \
                _Pragma("unroll")                                             \
                for (int k = 0; k < 4; ++k) {                                 \
                    float a = fmaxf(fmaf(e0[k], s0, fmaf(e1[k], s1, bb[k])), 0.f); \
                    a0a = fmaf(d0[k], a, a0a);                                \
                    a1a = fmaf(d1[k], a, a1a);                                \
                    ata = fmaf(w4[k], a, ata);                                \
                }                                                             \
                _Pragma("unroll")                                             \
                for (int k = 4; k < 7; ++k) {                                 \
                    float a = fmaxf(fmaf(e0[k], s0, fmaf(e1[k], s1, bb[k])), 0.f); \
                    a0b = fmaf(d0[k], a, a0b);                                \
                    a1b = fmaf(d1[k], a, a1b);                                \
                    atb = fmaf(w4[k], a, atb);                                \
                }                                                             \
                float a0 = a0a + a0b, a1 = a1a + a1b, at = ata + atb;         \
                a0 += __shfl_xor_sync(0xffffffffu, a0, 1, 8);                 \
                a1 += __shfl_xor_sync(0xffffffffu, a1, 1, 8);                 \
                at += __shfl_xor_sync(0xffffffffu, at, 1, 8);                 \
                a0 += __shfl_xor_sync(0xffffffffu, a0, 2, 8);                 \
                a1 += __shfl_xor_sync(0xffffffffu, a1, 2, 8);                 \
                at += __shfl_xor_sync(0xffffffffu, at, 2, 8);                 \
                a0 += __shfl_xor_sync(0xffffffffu, a0, 4, 8);                 \
                a1 += __shfl_xor_sync(0xffffffffu, a1, 4, 8);                 \
                s0 = fmaf(C_DT, a0, s0);                                      \
                s1 = fmaf(C_DT, a1, s1);                                      \
                if ((l8 & 3) == 0) slot[(sidx) * 128] = at;                   \
            }

            #pragma unroll 5
            for (int s = 0; s < C_HALF; ++s) OSC_STEP(s)

            __threadfence();
            __syncwarp();
            if (tid == 0) atomicAdd(&g_ph[0], 1u);      // publish phase 0

            #pragma unroll 5
            for (int s = C_HALF; s < C_STEPS; ++s) OSC_STEP(s)

            __threadfence();
            __syncwarp();
            if (tid == 0) atomicAdd(&g_ph[1], 1u);      // publish phase 1
#undef OSC_STEP
        }
    } else {
        // ============================ CONSUMER ============================
        __shared__ float sh_h[128];
        __shared__ float sh_direct;
        __shared__ float sh_torque[C_STEPS];
        __shared__ float sh_l[2 * C_STEPS];

        // h = relu(fc1 x + b1); warp0 computes direct (overlaps producers)
        {
            float v = fmaf(fc1_w[tid * 2], x0, fmaf(fc1_w[tid * 2 + 1], x1, fc1_b[tid]));
            sh_h[tid] = fmaxf(v, 0.f);
        }
        __syncthreads();
        if (tid < 32) {
            float s = 0.f;
            #pragma unroll
            for (int k = 0; k < 4; ++k)
                s = fmaf(fcd_w[tid + 32 * k], sh_h[tid + 32 * k], s);
            #pragma unroll
            for (int off = 16; off; off >>= 1)
                s += __shfl_down_sync(0xffffffffu, s, off);
            if (tid == 0) sh_direct = s + fcd_b[0] + fc4_b[0];
        }
        __syncthreads();
        const float direct = sh_direct;

        float th = x0, om = 0.f;        // tid 0's limb state across phases
        float sv = __sinf(x0);          // software-pipelined sine

        #pragma unroll
        for (int p = 0; p < 2; ++p) {
            // single-thread, single-line, sleepy poll (bounded: can't hang container)
            if (tid == 0) {
                unsigned v = 0;
                const unsigned* cp = &g_ph[p];
                for (long it = 0; it < 50000000L; ++it) {
                    asm volatile("ld.acquire.gpu.global.u32 %0, [%1];" : "=r"(v) : "l"(cp));
                    if (v >= NBP) break;
                    __nanosleep(64);
                }
            }
            __syncthreads();

            // 50 threads: reduce this phase's 104 quad-partials per step
            if (tid < C_HALF) {
                const int t = p * C_HALF + tid;
                const float4* row = (const float4*)(g_tq + t * 128);
                float acc = 0.f;
                #pragma unroll
                for (int j = 0; j < 26; ++j) {
                    float4 v = row[j];
                    acc += (v.x + v.y) + (v.z + v.w);
                }
                sh_torque[t] = acc + direct;
            }
            __syncthreads();

            // tid 0: limb integration for this phase (sin pipelined one step ahead)
            if (tid == 0) {
                #pragma unroll 5
                for (int i = 0; i < C_HALF; ++i) {
                    const int t = p * C_HALF + i;
                    float torque = sh_torque[t];
                    float th2 = fmaf(C_DT, om, th);
                    float om2 = fmaf(C_DT, torque - C_MGL2 * sv, om);
                    bool hit = (th2 > C_LIM) || (th2 < -C_LIM);
                    th2 = fminf(fmaxf(th2, -C_LIM), C_LIM);
                    om2 = hit ? 0.f : om2;
                    sh_l[2 * t]     = th2;
                    sh_l[2 * t + 1] = om2;
                    th = th2; om = om2;
                    sv = __sinf(th);
                }
            }
            __syncthreads();

            // write THIS phase's outputs now (overlaps producers' next phase):
            // l_states: out[p*100 .. p*100+99], torques: out[200+p*50 .. 200+p*50+49]
            if (tid < 100) out[p * 100 + tid] = sh_l[p * 100 + tid];
            if (tid < C_HALF) out[200 + p * C_HALF + tid] = sh_torque[p * C_HALF + tid];
        }

        // reset phase counters for the next graph replay (all producers done)
        if (tid < 2) g_ph[tid] = 0;
    }
}

extern "C" void kernel_launch(void* const* d_in, const int* in_sizes, int n_in,
                              void* d_out, int out_size) {
    const float* x        = (const float*)d_in[0];
    const float* fc1_w    = (const float*)d_in[1];
    const float* fc1_b    = (const float*)d_in[2];
    const float* fc2_w    = (const float*)d_in[3];
    const float* fc2_b    = (const float*)d_in[4];
    const float* fc3_w    = (const float*)d_in[5];
    const float* fc3_b    = (const float*)d_in[6];
    const float* fcd_w    = (const float*)d_in[7];
    const float* fcd_b    = (const float*)d_in[8];
    const float* fc4_w    = (const float*)d_in[9];
    const float* fc4_b    = (const float*)d_in[10];
    const float* enc      = (const float*)d_in[11];
    const float* osc_bias = (const float*)d_in[12];
    const float* dec      = (const float*)d_in[13];
    float* out = (float*)d_out;

    cpg_fused<<<NBP + 1, 128>>>(x, fc1_w, fc1_b, fc2_w, fc2_b, fc3_w, fc3_b,
                                fcd_w, fcd_b, fc4_w, fc4_b, enc, osc_bias, dec, out);
}

// round 16
// speedup vs baseline: 1.1180x; 1.0136x over previous
#include <cuda_runtime.h>
#include <math.h>

#define C_DT    0.01f
#define C_STEPS 100
#define C_HALF  50
#define C_NOSC  50
#define C_NPER  50
#define C_LIM   1.0471975511965976f   /* pi/3 */
#define C_MGL2  4.905f                /* m*g*(l/2), I = 1 */
#define NBP     13                    /* producer blocks: 4 oscillators each (52, 2 padded) */

/* [step][128]: slots bid*8 + q*2 + quad (104 used); never-written slots stay 0 */
__device__ __align__(128) float g_tq[C_STEPS * 128];
__device__ unsigned g_ph[2];          /* phase counters; consumer resets each run */

__global__ __launch_bounds__(256, 1)
void cpg_fused(const float* __restrict__ x,
               const float* __restrict__ fc1_w, const float* __restrict__ fc1_b,
               const float* __restrict__ fc2_w, const float* __restrict__ fc2_b,
               const float* __restrict__ fc3_w, const float* __restrict__ fc3_b,
               const float* __restrict__ fcd_w, const float* __restrict__ fcd_b,
               const float* __restrict__ fc4_w, const float* __restrict__ fc4_b,
               const float* __restrict__ enc,  const float* __restrict__ osc_bias,
               const float* __restrict__ dec,
               float* __restrict__ out)
{
    const int tid = threadIdx.x;
    const int bid = blockIdx.x;
    const float x0 = x[0], x1 = x[1];

    if (bid < NBP) {
        // ============================ PRODUCER ============================
        __shared__ float sh_h[128];
        __shared__ float sh_h2[128];
        __shared__ float sh_o[8];

        // warp0: per-neuron constants. 8 lanes/osc, 4 osc/warp, 7 neurons/lane.
        float e0[7], e1[7], bb[7], d0[7], d1[7], w4[7];
        if (tid < 32) {
            const int q   = tid >> 3;
            const int l8  = tid & 7;
            const int osc = bid * 4 + q;
            #pragma unroll
            for (int k = 0; k < 7; ++k) {
                int n = l8 + 8 * k;
                if (osc < C_NOSC && n < C_NPER) {
                    int idx = osc * C_NPER + n;
                    e0[k] = enc[idx * 2 + 0];
                    e1[k] = enc[idx * 2 + 1];
                    bb[k] = osc_bias[idx];
                    d0[k] = dec[osc * 2 * C_NPER + n];
                    d1[k] = dec[osc * 2 * C_NPER + C_NPER + n];
                    w4[k] = fc4_w[idx];
                } else {
                    e0[k] = e1[k] = bb[k] = d0[k] = d1[k] = w4[k] = 0.f;
                }
            }
        }

        // half-row pointer for fc2: 2 threads per row, 64 MACs each
        const int r2 = tid >> 1;           // row 0..127
        const int hf = tid & 1;            // half 0/1
        const float4* wr2 = (const float4*)(fc2_w + r2 * 128 + hf * 64);

        // prefetch 8 fc2 float4s above the first barrier (independent of h)
        float4 pre[8];
        #pragma unroll
        for (int j = 0; j < 8; ++j) pre[j] = wr2[j];

        // h = relu(fc1 x + b1): threads 0..127
        if (tid < 128) {
            float v = fmaf(fc1_w[tid * 2], x0, fmaf(fc1_w[tid * 2 + 1], x1, fc1_b[tid]));
            sh_h[tid] = fmaxf(v, 0.f);
        }
        __syncthreads();

        // h2 = relu(fc2 h + b2): 2 threads per row
        {
            const float* hv = sh_h + hf * 64;
            float a0 = 0.f, a1 = 0.f, a2 = 0.f, a3 = 0.f;
            #pragma unroll
            for (int j = 0; j < 8; ++j) {
                float4 w = pre[j];
                a0 = fmaf(w.x, hv[4 * j + 0], a0);
                a1 = fmaf(w.y, hv[4 * j + 1], a1);
                a2 = fmaf(w.z, hv[4 * j + 2], a2);
                a3 = fmaf(w.w, hv[4 * j + 3], a3);
            }
            #pragma unroll
            for (int j = 8; j < 16; ++j) {
                float4 w = wr2[j];
                a0 = fmaf(w.x, hv[4 * j + 0], a0);
                a1 = fmaf(w.y, hv[4 * j + 1], a1);
                a2 = fmaf(w.z, hv[4 * j + 2], a2);
                a3 = fmaf(w.w, hv[4 * j + 3], a3);
            }
            float s = (a0 + a1) + (a2 + a3);
            s += __shfl_down_sync(0xffffffffu, s, 1, 2);
            if (hf == 0) sh_h2[r2] = fmaxf(s + fc2_b[r2], 0.f);
        }
        __syncthreads();

        // warps 1-2 (tid 32..95): this block's 8 fc3 rows, 8 threads per row
        if (tid >= 32 && tid < 96) {
            const int r     = (tid - 32) >> 3;       // 0..7
            const int lane8 = tid & 7;
            const int row   = bid * 8 + r;
            float s = 0.f;
            if (row < 2 * C_NOSC) {
                const float* wr = fc3_w + row * 128 + lane8 * 16;
                const float* hv = sh_h2 + lane8 * 16;
                #pragma unroll
                for (int k = 0; k < 16; ++k) s = fmaf(wr[k], hv[k], s);
            }
            s += __shfl_down_sync(0xffffffffu, s, 4, 8);
            s += __shfl_down_sync(0xffffffffu, s, 2, 8);
            s += __shfl_down_sync(0xffffffffu, s, 1, 8);
            if (lane8 == 0) sh_o[r] = (row < 2 * C_NOSC) ? s + fc3_b[row] : 0.f;
        }
        __syncthreads();

        // warp0: 100-step recurrence, two branch-free 50-step halves.
        if (tid < 32) {
            const int q  = tid >> 3;
            const int l8 = tid & 7;
            float s0 = sh_o[2 * q];
            float s1 = sh_o[2 * q + 1];
            float* slot = g_tq + bid * 8 + q * 2 + (l8 >> 2);

#define OSC_STEP(sidx)                                                        \
            {                                                                 \
                float a0a = 0.f, a1a = 0.f, ata = 0.f;                        \
                float a0b = 0.f, a1b = 0.f, atb = 0.f;                        \
                _Pragma("unroll")                                             \
                for (int k = 0; k < 4; ++k) {                                 \
                    float a = fmaxf(fmaf(e0[k], s0, fmaf(e1[k], s1, bb[k])), 0.f); \
                    a0a = fmaf(d0[k], a, a0a);                                \
                    a1a = fmaf(d1[k], a, a1a);                                \
                    ata = fmaf(w4[k], a, ata);                                \
                }                                                             \
                _Pragma("unroll")                                             \
                for (int k = 4; k < 7; ++k) {                                 \
                    float a = fmaxf(fmaf(e0[k], s0, fmaf(e1[k], s1, bb[k])), 0.f); \
                    a0b = fmaf(d0[k], a, a0b);                                \
                    a1b = fmaf(d1[k], a, a1b);                                \
                    atb = fmaf(w4[k], a, atb);                                \
                }                                                             \
                float a0 = a0a + a0b, a1 = a1a + a1b, at = ata + atb;         \
                a0 += __shfl_xor_sync(0xffffffffu, a0, 1, 8);                 \
                a1 += __shfl_xor_sync(0xffffffffu, a1, 1, 8);                 \
                at += __shfl_xor_sync(0xffffffffu, at, 1, 8);                 \
                a0 += __shfl_xor_sync(0xffffffffu, a0, 2, 8);                 \
                a1 += __shfl_xor_sync(0xffffffffu, a1, 2, 8);                 \
                at += __shfl_xor_sync(0xffffffffu, at, 2, 8);                 \
                a0 += __shfl_xor_sync(0xffffffffu, a0, 4, 8);                 \
                a1 += __shfl_xor_sync(0xffffffffu, a1, 4, 8);                 \
                s0 = fmaf(C_DT, a0, s0);                                      \
                s1 = fmaf(C_DT, a1, s1);                                      \
                if ((l8 & 3) == 0) slot[(sidx) * 128] = at;                   \
            }

            #pragma unroll 5
            for (int s = 0; s < C_HALF; ++s) OSC_STEP(s)

            __threadfence();
            __syncwarp();
            if (tid == 0) atomicAdd(&g_ph[0], 1u);      // publish phase 0

            #pragma unroll 5
            for (int s = C_HALF; s < C_STEPS; ++s) OSC_STEP(s)

            __threadfence();
            __syncwarp();
            if (tid == 0) atomicAdd(&g_ph[1], 1u);      // publish phase 1
#undef OSC_STEP
        }
    } else {
        // ============================ CONSUMER ============================
        __shared__ float sh_h[128];
        __shared__ float sh_direct;
        __shared__ float sh_torque[C_STEPS];
        __shared__ float sh_l[2 * C_STEPS];

        // h = relu(fc1 x + b1); warp0 computes direct (overlaps producers)
        if (tid < 128) {
            float v = fmaf(fc1_w[tid * 2], x0, fmaf(fc1_w[tid * 2 + 1], x1, fc1_b[tid]));
            sh_h[tid] = fmaxf(v, 0.f);
        }
        __syncthreads();
        if (tid < 32) {
            float s = 0.f;
            #pragma unroll
            for (int k = 0; k < 4; ++k)
                s = fmaf(fcd_w[tid + 32 * k], sh_h[tid + 32 * k], s);
            #pragma unroll
            for (int off = 16; off; off >>= 1)
                s += __shfl_down_sync(0xffffffffu, s, off);
            if (tid == 0) sh_direct = s + fcd_b[0] + fc4_b[0];
        }
        __syncthreads();
        const float direct = sh_direct;

        float th = x0, om = 0.f;        // tid 0's limb state across phases
        float sv = __sinf(x0);          // software-pipelined sine

        #pragma unroll
        for (int p = 0; p < 2; ++p) {
            // single-thread, single-line, sleepy poll (bounded: can't hang container)
            if (tid == 0) {
                unsigned v = 0;
                const unsigned* cp = &g_ph[p];
                for (long it = 0; it < 50000000L; ++it) {
                    asm volatile("ld.acquire.gpu.global.u32 %0, [%1];" : "=r"(v) : "l"(cp));
                    if (v >= NBP) break;
                    __nanosleep(64);
                }
            }
            __syncthreads();

            // 50 threads: reduce this phase's 104 quad-partials per step
            if (tid < C_HALF) {
                const int t = p * C_HALF + tid;
                const float4* row = (const float4*)(g_tq + t * 128);
                float acc = 0.f;
                #pragma unroll
                for (int j = 0; j < 26; ++j) {
                    float4 v = row[j];
                    acc += (v.x + v.y) + (v.z + v.w);
                }
                sh_torque[t] = acc + direct;
            }
            __syncthreads();

            // tid 0: limb integration for this phase (sin pipelined one step ahead)
            if (tid == 0) {
                #pragma unroll 5
                for (int i = 0; i < C_HALF; ++i) {
                    const int t = p * C_HALF + i;
                    float torque = sh_torque[t];
                    float th2 = fmaf(C_DT, om, th);
                    float om2 = fmaf(C_DT, torque - C_MGL2 * sv, om);
                    bool hit = (th2 > C_LIM) || (th2 < -C_LIM);
                    th2 = fminf(fmaxf(th2, -C_LIM), C_LIM);
                    om2 = hit ? 0.f : om2;
                    sh_l[2 * t]     = th2;
                    sh_l[2 * t + 1] = om2;
                    th = th2; om = om2;
                    sv = __sinf(th);
                }
            }
            __syncthreads();

            // write THIS phase's outputs now (overlaps producers' next phase):
            // l_states: out[p*100 .. p*100+99], torques: out[200+p*50 .. 200+p*50+49]
            if (tid < 100) out[p * 100 + tid] = sh_l[p * 100 + tid];
            if (tid < C_HALF) out[200 + p * C_HALF + tid] = sh_torque[p * C_HALF + tid];
        }

        // reset phase counters for the next graph replay (all producers done)
        if (tid < 2) g_ph[tid] = 0;
    }
}

extern "C" void kernel_launch(void* const* d_in, const int* in_sizes, int n_in,
                              void* d_out, int out_size) {
    const float* x        = (const float*)d_in[0];
    const float* fc1_w    = (const float*)d_in[1];
    const float* fc1_b    = (const float*)d_in[2];
    const float* fc2_w    = (const float*)d_in[3];
    const float* fc2_b    = (const float*)d_in[4];
    const float* fc3_w    = (const float*)d_in[5];
    const float* fc3_b    = (const float*)d_in[6];
    const float* fcd_w    = (const float*)d_in[7];
    const float* fcd_b    = (const float*)d_in[8];
    const float* fc4_w    = (const float*)d_in[9];
    const float* fc4_b    = (const float*)d_in[10];
    const float* enc      = (const float*)d_in[11];
    const float* osc_bias = (const float*)d_in[12];
    const float* dec      = (const float*)d_in[13];
    float* out = (float*)d_out;

    cpg_fused<<<NBP + 1, 256>>>(x, fc1_w, fc1_b, fc2_w, fc2_b, fc3_w, fc3_b,
                                fcd_w, fcd_b, fc4_w, fc4_b, enc, osc_bias, dec, out);
}